// round 9
// baseline (speedup 1.0000x reference)
#include <cuda_runtime.h>
#include <cuda_fp16.h>
#include <cstdint>

#define NN 100000
#define EE 1600000
#define ET (EE + NN)
#define NEG_SLOPE 0.2f

// ---------------- scratch (static device globals; no runtime alloc) ----------
__device__ __half g_H1h[(size_t)NN * 128];  // layer1 linear output (fp16)
__device__ __half g_G1h[(size_t)NN * 128];  // layer1 final (relu, fp16)
__device__ __half g_H2h[(size_t)NN * 32];   // layer2 linear output (fp16)
__device__ float  g_AS1[NN * 4];
__device__ float  g_AD1[NN * 4];
__device__ float  g_AS2[NN];
__device__ float  g_AD2[NN];
__device__ int    g_deg[NN];
__device__ int    g_cur[NN];
__device__ int    g_off[NN + 1];
__device__ int    g_src[ET];
__device__ int    g_bsum[128];

__device__ __forceinline__ float lrelu(float v) { return v > 0.f ? v : NEG_SLOPE * v; }

// ---------------- tensor-core GEMM helpers ----------------------------------
__device__ __forceinline__ void ldsm_x4(uint32_t* r, uint32_t addr) {
    asm volatile("ldmatrix.sync.aligned.m8n8.x4.shared.b16 {%0,%1,%2,%3}, [%4];"
                 : "=r"(r[0]), "=r"(r[1]), "=r"(r[2]), "=r"(r[3]) : "r"(addr));
}
__device__ __forceinline__ void ldsm_x4_t(uint32_t* r, uint32_t addr) {
    asm volatile("ldmatrix.sync.aligned.m8n8.x4.trans.shared.b16 {%0,%1,%2,%3}, [%4];"
                 : "=r"(r[0]), "=r"(r[1]), "=r"(r[2]), "=r"(r[3]) : "r"(addr));
}
__device__ __forceinline__ void mma16816(float* d, const uint32_t* a, const uint32_t* b) {
    asm volatile("mma.sync.aligned.m16n8k16.row.col.f32.f16.f16.f32 "
                 "{%0,%1,%2,%3}, {%4,%5,%6,%7}, {%8,%9}, {%0,%1,%2,%3};"
                 : "+f"(d[0]), "+f"(d[1]), "+f"(d[2]), "+f"(d[3])
                 : "r"(a[0]), "r"(a[1]), "r"(a[2]), "r"(a[3]), "r"(b[0]), "r"(b[1]));
}

// C[M,BN] = fp16(A[M,128] * B[128,BN]); K=128 one-shot; 256 threads.
// Warp tile WM=BM/WARPS_M x WN=BN/WARPS_N, with WN == 32 == one head.
// Fused epilogue: AS[r*H+head] = sum_c C[r,c]*a_s[c], AD likewise (fp32 accs).
template <typename AT, int BM, int BN, int WARPS_M, int WARPS_N, int H>
__global__ void __launch_bounds__(256)
hgemm_kernel(const AT* __restrict__ A, const float* __restrict__ B,
             __half* __restrict__ C,
             const float* __restrict__ a_s, const float* __restrict__ a_d,
             float* __restrict__ AS, float* __restrict__ AD, int M) {
    constexpr int K  = 128;
    constexpr int SA = K + 8;
    constexpr int SB = BN + 8;
    constexpr int WM = BM / WARPS_M;
    constexpr int WN = BN / WARPS_N;    // must be 32
    constexpr int MT = WM / 16;
    constexpr int NT = WN / 8;          // 4

    extern __shared__ __half smem[];
    __half* As = smem;             // [BM][SA]
    __half* Bs = smem + BM * SA;   // [K][SB]

    int t  = threadIdx.x;
    int bm = blockIdx.x * BM;

    // ---- A tile: linear coalesced load (rows contiguous, K==row stride) ----
    if constexpr (sizeof(AT) == 4) {
        const float4* Ag = (const float4*)A + (size_t)bm * 32;
#pragma unroll
        for (int i = 0; i < BM / 8; i++) {
            int idx = t + i * 256;
            int row = idx >> 5;
            int col = (idx & 31) * 4;
            float4 v = (bm + row < M) ? Ag[idx] : make_float4(0.f, 0.f, 0.f, 0.f);
            __half2* d = (__half2*)(As + row * SA + col);
            d[0] = __floats2half2_rn(v.x, v.y);
            d[1] = __floats2half2_rn(v.z, v.w);
        }
    } else {
        const uint4* Ag = (const uint4*)A + (size_t)bm * 16;
#pragma unroll
        for (int i = 0; i < BM / 16; i++) {
            int idx = t + i * 256;
            int row = idx >> 4;
            int col = (idx & 15) * 8;
            uint4 v = (bm + row < M) ? Ag[idx] : make_uint4(0, 0, 0, 0);
            *(uint4*)(As + row * SA + col) = v;
        }
    }
    // ---- B tile [K][BN] fp32 -> fp16, linear coalesced ----
    {
        constexpr int BPR = BN / 4;
        const float4* Bg = (const float4*)B;
#pragma unroll
        for (int i = 0; i < K * BN / 1024; i++) {
            int idx = t + i * 256;
            int row = idx / BPR;
            int col = (idx % BPR) * 4;
            float4 v = Bg[idx];
            __half2* d = (__half2*)(Bs + row * SB + col);
            d[0] = __floats2half2_rn(v.x, v.y);
            d[1] = __floats2half2_rn(v.z, v.w);
        }
    }
    __syncthreads();

    int warp = t >> 5, lane = t & 31;
    int wm = (warp % WARPS_M) * WM;
    int wn = (warp / WARPS_M) * WN;

    float acc[MT][NT][4];
#pragma unroll
    for (int i = 0; i < MT; i++)
#pragma unroll
        for (int j = 0; j < NT; j++)
#pragma unroll
            for (int q = 0; q < 4; q++) acc[i][j][q] = 0.f;

    uint32_t a_base = (uint32_t)__cvta_generic_to_shared(As);
    uint32_t b_base = (uint32_t)__cvta_generic_to_shared(Bs);

#pragma unroll
    for (int ks = 0; ks < 8; ks++) {
        int k0 = ks * 16;
        uint32_t af[MT][4];
#pragma unroll
        for (int mt = 0; mt < MT; mt++) {
            int row = wm + mt * 16 + (lane & 15);
            int col = k0 + (lane >> 4) * 8;
            ldsm_x4(af[mt], a_base + (row * SA + col) * 2);
        }
        uint32_t bf[NT][2];
#pragma unroll
        for (int nt = 0; nt < NT; nt += 2) {
            int row = k0 + (lane & 15);
            int col = wn + nt * 8 + (lane >> 4) * 8;
            uint32_t r[4];
            ldsm_x4_t(r, b_base + (row * SB + col) * 2);
            bf[nt][0] = r[0]; bf[nt][1] = r[1];
            bf[nt + 1][0] = r[2]; bf[nt + 1][1] = r[3];
        }
#pragma unroll
        for (int mt = 0; mt < MT; mt++)
#pragma unroll
            for (int nt = 0; nt < NT; nt++) mma16816(acc[mt][nt], af[mt], bf[nt]);
    }

    // ---- epilogue: fp16 store + fused alpha ----
    int head = wn >> 5;
    float2 asv[NT], adv[NT];
#pragma unroll
    for (int nt = 0; nt < NT; nt++) {
        int c = wn + nt * 8 + (lane & 3) * 2;
        asv[nt] = *(const float2*)&a_s[c];
        adv[nt] = *(const float2*)&a_d[c];
    }
#pragma unroll
    for (int mt = 0; mt < MT; mt++) {
        int r0 = bm + wm + mt * 16 + (lane >> 2);
        int r1 = r0 + 8;
        float sAl = 0.f, sDl = 0.f, sAh = 0.f, sDh = 0.f;
#pragma unroll
        for (int nt = 0; nt < NT; nt++) {
            int col = wn + nt * 8 + (lane & 3) * 2;
            if (r0 < M)
                *(__half2*)&C[(size_t)r0 * BN + col] = __floats2half2_rn(acc[mt][nt][0], acc[mt][nt][1]);
            if (r1 < M)
                *(__half2*)&C[(size_t)r1 * BN + col] = __floats2half2_rn(acc[mt][nt][2], acc[mt][nt][3]);
            sAl += acc[mt][nt][0] * asv[nt].x + acc[mt][nt][1] * asv[nt].y;
            sDl += acc[mt][nt][0] * adv[nt].x + acc[mt][nt][1] * adv[nt].y;
            sAh += acc[mt][nt][2] * asv[nt].x + acc[mt][nt][3] * asv[nt].y;
            sDh += acc[mt][nt][2] * adv[nt].x + acc[mt][nt][3] * adv[nt].y;
        }
#pragma unroll
        for (int o = 1; o <= 2; o <<= 1) {
            sAl += __shfl_xor_sync(0xffffffffu, sAl, o);
            sDl += __shfl_xor_sync(0xffffffffu, sDl, o);
            sAh += __shfl_xor_sync(0xffffffffu, sAh, o);
            sDh += __shfl_xor_sync(0xffffffffu, sDh, o);
        }
        if ((lane & 3) == 0) {
            if (r0 < M) { AS[r0 * H + head] = sAl; AD[r0 * H + head] = sDl; }
            if (r1 < M) { AS[r1 * H + head] = sAh; AD[r1 * H + head] = sDh; }
        }
    }
}

// ---------------- CSR build ----------------
__global__ void init_kernel() {
    int i = blockIdx.x * blockDim.x + threadIdx.x;
    if (i < NN) {
        g_deg[i] = 1;
        g_cur[i] = 0;
    }
    if (i == 0) g_off[0] = 0;
}

__global__ void hist_kernel(const int* __restrict__ ei) {
    int e = blockIdx.x * blockDim.x + threadIdx.x;
    if (e < EE) atomicAdd(&g_deg[ei[EE + e]], 1);
}

__global__ void scan_blocks_kernel(int n) {
    __shared__ int wsum[32];
    int i = blockIdx.x * 1024 + threadIdx.x;
    int lane = threadIdx.x & 31, wid = threadIdx.x >> 5;
    int x = (i < n) ? g_deg[i] : 0;
#pragma unroll
    for (int o = 1; o < 32; o <<= 1) {
        int y = __shfl_up_sync(0xffffffffu, x, o);
        if (lane >= o) x += y;
    }
    if (lane == 31) wsum[wid] = x;
    __syncthreads();
    if (wid == 0) {
        int s = wsum[lane];
#pragma unroll
        for (int o = 1; o < 32; o <<= 1) {
            int y = __shfl_up_sync(0xffffffffu, s, o);
            if (lane >= o) s += y;
        }
        wsum[lane] = s;
    }
    __syncthreads();
    int inc = x + (wid > 0 ? wsum[wid - 1] : 0);
    if (i < n) g_off[i + 1] = inc;
    if (threadIdx.x == 1023) g_bsum[blockIdx.x] = inc;
}

__global__ void scan_top_kernel(int nb) {
    __shared__ int sh[128];
    int t = threadIdx.x;
    sh[t] = (t < nb) ? g_bsum[t] : 0;
    __syncthreads();
#pragma unroll
    for (int o = 1; o < 128; o <<= 1) {
        int y = (t >= o) ? sh[t - o] : 0;
        __syncthreads();
        sh[t] += y;
        __syncthreads();
    }
    if (t < nb) g_bsum[t] = (t > 0) ? sh[t - 1] : 0;
}

__global__ void scan_add_kernel(int n) {
    int i = blockIdx.x * blockDim.x + threadIdx.x;
    if (i < n) g_off[i + 1] += g_bsum[i >> 10];
}

__global__ void scatter_kernel(const int* __restrict__ ei) {
    int e = blockIdx.x * blockDim.x + threadIdx.x;
    if (e < EE) {
        int s = ei[e];
        int d = ei[EE + e];
        int p = g_off[d] + atomicAdd(&g_cur[d], 1);
        g_src[p] = s;
    } else if (e < ET) {
        int nd = e - EE;
        int p = g_off[nd] + atomicAdd(&g_cur[nd], 1);
        g_src[p] = nd;
    }
}

// ---------------- layer1 aggregation: fused single pass, 8-edge chunks ------
__global__ void agg1_kernel(const float* __restrict__ b1) {
    int node = (blockIdx.x * blockDim.x + threadIdx.x) >> 5;
    int lane = threadIdx.x & 31;
    if (node >= NN) return;
    int beg = g_off[node], end = g_off[node + 1];
    int h  = lane & 3;
    int e  = lane >> 2;
    int hd = lane >> 3;
    float adH = g_AD1[node * 4 + h];

    float4 acc = make_float4(0.f, 0.f, 0.f, 0.f);
    float den = 0.f;

    for (int base = beg; base < end; base += 8) {
        int idx = base + e;
        bool valid = idx < end;
        int s = valid ? g_src[idx] : 0;
        float w = 0.f;
        if (valid) w = __expf(lrelu(g_AS1[s * 4 + h] + adH));
        den += w;
#pragma unroll
        for (int e2 = 0; e2 < 8; e2++) {
            int   ss = __shfl_sync(0xffffffffu, s, e2 * 4);
            float ww = __shfl_sync(0xffffffffu, w, e2 * 4 + hd);
            uint2 u = *(const uint2*)(g_H1h + (size_t)ss * 128 + lane * 4);
            float2 fa = __half22float2(*(__half2*)&u.x);
            float2 fb = __half22float2(*(__half2*)&u.y);
            acc.x = fmaf(ww, fa.x, acc.x);
            acc.y = fmaf(ww, fa.y, acc.y);
            acc.z = fmaf(ww, fb.x, acc.z);
            acc.w = fmaf(ww, fb.y, acc.w);
        }
    }
    den += __shfl_xor_sync(0xffffffffu, den, 4);
    den += __shfl_xor_sync(0xffffffffu, den, 8);
    den += __shfl_xor_sync(0xffffffffu, den, 16);
    float inv = 1.f / __shfl_sync(0xffffffffu, den, hd);

    float4 bb = *(const float4*)&b1[lane * 4];
    float r0 = fmaxf(fmaf(acc.x, inv, bb.x), 0.f);
    float r1 = fmaxf(fmaf(acc.y, inv, bb.y), 0.f);
    float r2 = fmaxf(fmaf(acc.z, inv, bb.z), 0.f);
    float r3 = fmaxf(fmaf(acc.w, inv, bb.w), 0.f);
    __half2* dst = (__half2*)(g_G1h + (size_t)node * 128 + lane * 4);
    dst[0] = __floats2half2_rn(r0, r1);
    dst[1] = __floats2half2_rn(r2, r3);
}

// ---------------- layer2 aggregation: fused single pass, 16-edge chunks -----
__global__ void agg2_kernel(const float* __restrict__ b2, float* __restrict__ out) {
    int node = (blockIdx.x * blockDim.x + threadIdx.x) >> 5;
    int lane = threadIdx.x & 31;
    if (node >= NN) return;
    int beg = g_off[node], end = g_off[node + 1];
    float ad = g_AD2[node];
    int e = lane & 15;

    float acc = 0.f, den = 0.f;
    for (int base = beg; base < end; base += 16) {
        int idx = base + e;
        bool valid = idx < end;
        int s = valid ? g_src[idx] : 0;
        float w = 0.f;
        if (valid) w = __expf(lrelu(g_AS2[s] + ad));
        if (lane < 16) den += w;
#pragma unroll
        for (int e2 = 0; e2 < 16; e2++) {
            int   ss = __shfl_sync(0xffffffffu, s, e2);
            float ww = __shfl_sync(0xffffffffu, w, e2);
            float hv = __half2float(g_H2h[(size_t)ss * 32 + lane]);
            acc = fmaf(ww, hv, acc);
        }
    }
#pragma unroll
    for (int o = 16; o; o >>= 1) den += __shfl_xor_sync(0xffffffffu, den, o);
    float inv = 1.f / den;
    out[(size_t)node * 32 + lane] = fmaf(acc, inv, b2[lane]);
}

// ---------------- launch (single stream) ----------------
extern "C" void kernel_launch(void* const* d_in, const int* in_sizes, int n_in,
                              void* d_out, int out_size) {
    const float* x    = (const float*)d_in[0];
    const int*   ei   = (const int*)d_in[1];
    const float* W1   = (const float*)d_in[2];
    const float* as1  = (const float*)d_in[3];
    const float* ad1  = (const float*)d_in[4];
    const float* b1   = (const float*)d_in[5];
    const float* W2   = (const float*)d_in[6];
    const float* as2  = (const float*)d_in[7];
    const float* ad2  = (const float*)d_in[8];
    const float* b2   = (const float*)d_in[9];
    float* out = (float*)d_out;

    __half* H1h; cudaGetSymbolAddress((void**)&H1h, g_H1h);
    __half* G1h; cudaGetSymbolAddress((void**)&G1h, g_G1h);
    __half* H2h; cudaGetSymbolAddress((void**)&H2h, g_H2h);
    float*  AS1; cudaGetSymbolAddress((void**)&AS1, g_AS1);
    float*  AD1; cudaGetSymbolAddress((void**)&AD1, g_AD1);
    float*  AS2; cudaGetSymbolAddress((void**)&AS2, g_AS2);
    float*  AD2; cudaGetSymbolAddress((void**)&AD2, g_AD2);

    const int NB = (NN + 1023) / 1024;
    const int smem1 = (64 * 136 + 128 * 136) * 2;   // 52224 B
    const int smem2 = (128 * 136 + 128 * 40) * 2;   // 45056 B

    cudaFuncSetAttribute((const void*)hgemm_kernel<float, 64, 128, 2, 4, 4>,
                         cudaFuncAttributeMaxDynamicSharedMemorySize, smem1);
    cudaFuncSetAttribute((const void*)hgemm_kernel<__half, 128, 32, 8, 1, 1>,
                         cudaFuncAttributeMaxDynamicSharedMemorySize, smem2);

    // Launch order keeps hgemm1 in the ncu-profiled slot (4th launch).
    init_kernel<<<(NN + 255) / 256, 256>>>();                        // 0
    hist_kernel<<<(EE + 255) / 256, 256>>>(ei);                      // 1
    scan_blocks_kernel<<<NB, 1024>>>(NN);                            // 2
    hgemm_kernel<float, 64, 128, 2, 4, 4>                            // 3 <- profiled
        <<<(NN + 63) / 64, 256, smem1>>>(x, W1, H1h, as1, ad1, AS1, AD1, NN);
    scan_top_kernel<<<1, 128>>>(NB);                                 // 4
    scan_add_kernel<<<(NN + 255) / 256, 256>>>(NN);                  // 5
    scatter_kernel<<<(ET + 255) / 256, 256>>>(ei);                   // 6
    agg1_kernel<<<(NN * 32 + 255) / 256, 256>>>(b1);                 // 7
    hgemm_kernel<__half, 128, 32, 8, 1, 1>                           // 8
        <<<(NN + 127) / 128, 256, smem2>>>(G1h, W2, H2h, as2, ad2, AS2, AD2, NN);
    agg2_kernel<<<(NN * 32 + 255) / 256, 256>>>(b2, out);            // 9
}

// round 10
// speedup vs baseline: 1.0243x; 1.0243x over previous
#include <cuda_runtime.h>
#include <cuda_fp16.h>
#include <cstdint>

#define NN 100000
#define EE 1600000
#define ET (EE + NN)
#define NEG_SLOPE 0.2f

// ---------------- scratch (static device globals; zero-initialized) ---------
__device__ __half g_H1h[(size_t)NN * 128];
__device__ __half g_G1h[(size_t)NN * 128];
__device__ __half g_H2h[(size_t)NN * 32];
__device__ float  g_AS1[NN * 4];
__device__ float  g_AD1[NN * 4];
__device__ float  g_AS2[NN];
__device__ float  g_AD2[NN];
__device__ int    g_deg[NN];      // invariant: zero at start of every replay
__device__ int    g_cur[NN];      // zeroed by scan_addtop before scatter
__device__ int    g_off[NN + 1];  // g_off[0] stays 0 forever
__device__ int    g_src[ET];
__device__ int    g_bsum[128];

__device__ __forceinline__ float lrelu(float v) { return v > 0.f ? v : NEG_SLOPE * v; }

// ---------------- tensor-core GEMM helpers ----------------------------------
__device__ __forceinline__ void ldsm_x4(uint32_t* r, uint32_t addr) {
    asm volatile("ldmatrix.sync.aligned.m8n8.x4.shared.b16 {%0,%1,%2,%3}, [%4];"
                 : "=r"(r[0]), "=r"(r[1]), "=r"(r[2]), "=r"(r[3]) : "r"(addr));
}
__device__ __forceinline__ void ldsm_x4_t(uint32_t* r, uint32_t addr) {
    asm volatile("ldmatrix.sync.aligned.m8n8.x4.trans.shared.b16 {%0,%1,%2,%3}, [%4];"
                 : "=r"(r[0]), "=r"(r[1]), "=r"(r[2]), "=r"(r[3]) : "r"(addr));
}
__device__ __forceinline__ void mma16816(float* d, const uint32_t* a, const uint32_t* b) {
    asm volatile("mma.sync.aligned.m16n8k16.row.col.f32.f16.f16.f32 "
                 "{%0,%1,%2,%3}, {%4,%5,%6,%7}, {%8,%9}, {%0,%1,%2,%3};"
                 : "+f"(d[0]), "+f"(d[1]), "+f"(d[2]), "+f"(d[3])
                 : "r"(a[0]), "r"(a[1]), "r"(a[2]), "r"(a[3]), "r"(b[0]), "r"(b[1]));
}

// GEMM device body: C[M,BN] = fp16(A[M,128]*B[128,BN]), fused alpha epilogue.
template <typename AT, int BM, int BN, int WARPS_M, int WARPS_N, int H>
__device__ __forceinline__ void gemm_dev(
    __half* smem, int blk,
    const AT* __restrict__ A, const float* __restrict__ B, __half* __restrict__ C,
    const float* __restrict__ a_s, const float* __restrict__ a_d,
    float* __restrict__ AS, float* __restrict__ AD, int M) {
    constexpr int K  = 128;
    constexpr int SA = K + 8;
    constexpr int SB = BN + 8;
    constexpr int WM = BM / WARPS_M;
    constexpr int WN = BN / WARPS_N;    // == 32 (one head)
    constexpr int MT = WM / 16;
    constexpr int NT = WN / 8;

    __half* As = smem;
    __half* Bs = smem + BM * SA;

    int t  = threadIdx.x;
    int bm = blk * BM;

    if constexpr (sizeof(AT) == 4) {
        const float4* Ag = (const float4*)A + (size_t)bm * 32;
#pragma unroll
        for (int i = 0; i < BM / 8; i++) {
            int idx = t + i * 256;
            int row = idx >> 5;
            int col = (idx & 31) * 4;
            float4 v = (bm + row < M) ? Ag[idx] : make_float4(0.f, 0.f, 0.f, 0.f);
            __half2* d = (__half2*)(As + row * SA + col);
            d[0] = __floats2half2_rn(v.x, v.y);
            d[1] = __floats2half2_rn(v.z, v.w);
        }
    } else {
        const uint4* Ag = (const uint4*)A + (size_t)bm * 16;
#pragma unroll
        for (int i = 0; i < BM / 16; i++) {
            int idx = t + i * 256;
            int row = idx >> 4;
            int col = (idx & 15) * 8;
            uint4 v = (bm + row < M) ? Ag[idx] : make_uint4(0, 0, 0, 0);
            *(uint4*)(As + row * SA + col) = v;
        }
    }
    {
        constexpr int BPR = BN / 4;
        const float4* Bg = (const float4*)B;
#pragma unroll
        for (int i = 0; i < K * BN / 1024; i++) {
            int idx = t + i * 256;
            int row = idx / BPR;
            int col = (idx % BPR) * 4;
            float4 v = Bg[idx];
            __half2* d = (__half2*)(Bs + row * SB + col);
            d[0] = __floats2half2_rn(v.x, v.y);
            d[1] = __floats2half2_rn(v.z, v.w);
        }
    }
    __syncthreads();

    int warp = t >> 5, lane = t & 31;
    int wm = (warp % WARPS_M) * WM;
    int wn = (warp / WARPS_M) * WN;

    float acc[MT][NT][4];
#pragma unroll
    for (int i = 0; i < MT; i++)
#pragma unroll
        for (int j = 0; j < NT; j++)
#pragma unroll
            for (int q = 0; q < 4; q++) acc[i][j][q] = 0.f;

    uint32_t a_base = (uint32_t)__cvta_generic_to_shared(As);
    uint32_t b_base = (uint32_t)__cvta_generic_to_shared(Bs);

#pragma unroll
    for (int ks = 0; ks < 8; ks++) {
        int k0 = ks * 16;
        uint32_t af[MT][4];
#pragma unroll
        for (int mt = 0; mt < MT; mt++) {
            int row = wm + mt * 16 + (lane & 15);
            int col = k0 + (lane >> 4) * 8;
            ldsm_x4(af[mt], a_base + (row * SA + col) * 2);
        }
        uint32_t bf[NT][2];
#pragma unroll
        for (int nt = 0; nt < NT; nt += 2) {
            int row = k0 + (lane & 15);
            int col = wn + nt * 8 + (lane >> 4) * 8;
            uint32_t r[4];
            ldsm_x4_t(r, b_base + (row * SB + col) * 2);
            bf[nt][0] = r[0]; bf[nt][1] = r[1];
            bf[nt + 1][0] = r[2]; bf[nt + 1][1] = r[3];
        }
#pragma unroll
        for (int mt = 0; mt < MT; mt++)
#pragma unroll
            for (int nt = 0; nt < NT; nt++) mma16816(acc[mt][nt], af[mt], bf[nt]);
    }

    int head = wn >> 5;
    float2 asv[NT], adv[NT];
#pragma unroll
    for (int nt = 0; nt < NT; nt++) {
        int c = wn + nt * 8 + (lane & 3) * 2;
        asv[nt] = *(const float2*)&a_s[c];
        adv[nt] = *(const float2*)&a_d[c];
    }
#pragma unroll
    for (int mt = 0; mt < MT; mt++) {
        int r0 = bm + wm + mt * 16 + (lane >> 2);
        int r1 = r0 + 8;
        float sAl = 0.f, sDl = 0.f, sAh = 0.f, sDh = 0.f;
#pragma unroll
        for (int nt = 0; nt < NT; nt++) {
            int col = wn + nt * 8 + (lane & 3) * 2;
            if (r0 < M)
                *(__half2*)&C[(size_t)r0 * BN + col] = __floats2half2_rn(acc[mt][nt][0], acc[mt][nt][1]);
            if (r1 < M)
                *(__half2*)&C[(size_t)r1 * BN + col] = __floats2half2_rn(acc[mt][nt][2], acc[mt][nt][3]);
            sAl += acc[mt][nt][0] * asv[nt].x + acc[mt][nt][1] * asv[nt].y;
            sDl += acc[mt][nt][0] * adv[nt].x + acc[mt][nt][1] * adv[nt].y;
            sAh += acc[mt][nt][2] * asv[nt].x + acc[mt][nt][3] * asv[nt].y;
            sDh += acc[mt][nt][2] * adv[nt].x + acc[mt][nt][3] * adv[nt].y;
        }
#pragma unroll
        for (int o = 1; o <= 2; o <<= 1) {
            sAl += __shfl_xor_sync(0xffffffffu, sAl, o);
            sDl += __shfl_xor_sync(0xffffffffu, sDl, o);
            sAh += __shfl_xor_sync(0xffffffffu, sAh, o);
            sDh += __shfl_xor_sync(0xffffffffu, sDh, o);
        }
        if ((lane & 3) == 0) {
            if (r0 < M) { AS[r0 * H + head] = sAl; AD[r0 * H + head] = sDl; }
            if (r1 < M) { AS[r1 * H + head] = sAh; AD[r1 * H + head] = sDh; }
        }
    }
}

// ---------------- fused: GEMM1 (blocks < GB) + degree histogram (rest) ------
template <int GB, int HB>
__global__ void __launch_bounds__(256) gemm1_hist_kernel(
    const float* __restrict__ A, const float* __restrict__ B, __half* __restrict__ C,
    const float* __restrict__ a_s, const float* __restrict__ a_d,
    float* __restrict__ AS, float* __restrict__ AD, int M,
    const int* __restrict__ ei) {
    extern __shared__ __half smem[];
    if (blockIdx.x < GB) {
        gemm_dev<float, 64, 128, 2, 4, 4>(smem, blockIdx.x, A, B, C, a_s, a_d, AS, AD, M);
    } else {
        int tid = (blockIdx.x - GB) * 256 + threadIdx.x;
        const int4* d4 = (const int4*)(ei + EE);
        for (int i = tid; i < EE / 4; i += HB * 256) {
            int4 v = d4[i];
            atomicAdd(&g_deg[v.x], 1);
            atomicAdd(&g_deg[v.y], 1);
            atomicAdd(&g_deg[v.z], 1);
            atomicAdd(&g_deg[v.w], 1);
        }
    }
}

// ---------------- standalone GEMM2 ------------------------------------------
template <typename AT, int BM, int BN, int WARPS_M, int WARPS_N, int H>
__global__ void __launch_bounds__(256) hgemm_kernel(
    const AT* __restrict__ A, const float* __restrict__ B, __half* __restrict__ C,
    const float* __restrict__ a_s, const float* __restrict__ a_d,
    float* __restrict__ AS, float* __restrict__ AD, int M) {
    extern __shared__ __half smem[];
    gemm_dev<AT, BM, BN, WARPS_M, WARPS_N, H>(smem, blockIdx.x, A, B, C, a_s, a_d, AS, AD, M);
}

// ---------------- CSR: per-block scan (deg+1), resets deg to 0 --------------
__global__ void scan_blocks_kernel(int n) {
    __shared__ int wsum[32];
    int i = blockIdx.x * 1024 + threadIdx.x;
    int lane = threadIdx.x & 31, wid = threadIdx.x >> 5;
    int x = (i < n) ? g_deg[i] + 1 : 0;   // +1 = self-loop (init folded in)
#pragma unroll
    for (int o = 1; o < 32; o <<= 1) {
        int y = __shfl_up_sync(0xffffffffu, x, o);
        if (lane >= o) x += y;
    }
    if (lane == 31) wsum[wid] = x;
    __syncthreads();
    if (wid == 0) {
        int s = wsum[lane];
#pragma unroll
        for (int o = 1; o < 32; o <<= 1) {
            int y = __shfl_up_sync(0xffffffffu, s, o);
            if (lane >= o) s += y;
        }
        wsum[lane] = s;
    }
    __syncthreads();
    int inc = x + (wid > 0 ? wsum[wid - 1] : 0);
    if (i < n) {
        g_off[i + 1] = inc;
        g_deg[i] = 0;                      // restore zero-invariant for next replay
    }
    if (threadIdx.x == 1023) g_bsum[blockIdx.x] = inc;
}

// ---------------- CSR: fused top-scan + apply (every block re-scans bsums) --
__global__ void scan_addtop_kernel(int nb, int n) {
    __shared__ int sh[128];
    int t = threadIdx.x;
    if (t < 128) sh[t] = (t < nb) ? g_bsum[t] : 0;
    __syncthreads();
#pragma unroll
    for (int o = 1; o < 128; o <<= 1) {
        int y = (t < 128 && t >= o) ? sh[t - o] : 0;
        __syncthreads();
        if (t < 128) sh[t] += y;
        __syncthreads();
    }
    int i = blockIdx.x * 256 + t;
    if (i < n) {
        int g = i >> 10;
        int add = (g > 0) ? sh[g - 1] : 0;
        g_off[i + 1] += add;
        g_cur[i] = 0;                      // zero cursor for scatter
    }
}

__global__ void scatter_kernel(const int* __restrict__ ei) {
    int e = blockIdx.x * blockDim.x + threadIdx.x;
    if (e < EE) {
        int s = ei[e];
        int d = ei[EE + e];
        int p = g_off[d] + atomicAdd(&g_cur[d], 1);
        g_src[p] = s;
    } else if (e < ET) {
        int nd = e - EE;
        int p = g_off[nd] + atomicAdd(&g_cur[nd], 1);
        g_src[p] = nd;
    }
}

// ---------------- layer1 aggregation ----------------------------------------
__global__ void agg1_kernel(const float* __restrict__ b1) {
    int node = (blockIdx.x * blockDim.x + threadIdx.x) >> 5;
    int lane = threadIdx.x & 31;
    if (node >= NN) return;
    int beg = g_off[node], end = g_off[node + 1];
    int h  = lane & 3;
    int e  = lane >> 2;
    int hd = lane >> 3;
    float adH = g_AD1[node * 4 + h];

    float4 acc = make_float4(0.f, 0.f, 0.f, 0.f);
    float den = 0.f;

    for (int base = beg; base < end; base += 8) {
        int idx = base + e;
        bool valid = idx < end;
        int s = valid ? g_src[idx] : 0;
        float w = 0.f;
        if (valid) w = __expf(lrelu(g_AS1[s * 4 + h] + adH));
        den += w;
#pragma unroll
        for (int e2 = 0; e2 < 8; e2++) {
            int   ss = __shfl_sync(0xffffffffu, s, e2 * 4);
            float ww = __shfl_sync(0xffffffffu, w, e2 * 4 + hd);
            uint2 u = *(const uint2*)(g_H1h + (size_t)ss * 128 + lane * 4);
            float2 fa = __half22float2(*(__half2*)&u.x);
            float2 fb = __half22float2(*(__half2*)&u.y);
            acc.x = fmaf(ww, fa.x, acc.x);
            acc.y = fmaf(ww, fa.y, acc.y);
            acc.z = fmaf(ww, fb.x, acc.z);
            acc.w = fmaf(ww, fb.y, acc.w);
        }
    }
    den += __shfl_xor_sync(0xffffffffu, den, 4);
    den += __shfl_xor_sync(0xffffffffu, den, 8);
    den += __shfl_xor_sync(0xffffffffu, den, 16);
    float inv = 1.f / __shfl_sync(0xffffffffu, den, hd);

    float4 bb = *(const float4*)&b1[lane * 4];
    float r0 = fmaxf(fmaf(acc.x, inv, bb.x), 0.f);
    float r1 = fmaxf(fmaf(acc.y, inv, bb.y), 0.f);
    float r2 = fmaxf(fmaf(acc.z, inv, bb.z), 0.f);
    float r3 = fmaxf(fmaf(acc.w, inv, bb.w), 0.f);
    __half2* dst = (__half2*)(g_G1h + (size_t)node * 128 + lane * 4);
    dst[0] = __floats2half2_rn(r0, r1);
    dst[1] = __floats2half2_rn(r2, r3);
}

// ---------------- layer2 aggregation ----------------------------------------
__global__ void agg2_kernel(const float* __restrict__ b2, float* __restrict__ out) {
    int node = (blockIdx.x * blockDim.x + threadIdx.x) >> 5;
    int lane = threadIdx.x & 31;
    if (node >= NN) return;
    int beg = g_off[node], end = g_off[node + 1];
    float ad = g_AD2[node];
    int e = lane & 15;

    float acc = 0.f, den = 0.f;
    for (int base = beg; base < end; base += 16) {
        int idx = base + e;
        bool valid = idx < end;
        int s = valid ? g_src[idx] : 0;
        float w = 0.f;
        if (valid) w = __expf(lrelu(g_AS2[s] + ad));
        if (lane < 16) den += w;
#pragma unroll
        for (int e2 = 0; e2 < 16; e2++) {
            int   ss = __shfl_sync(0xffffffffu, s, e2);
            float ww = __shfl_sync(0xffffffffu, w, e2);
            float hv = __half2float(g_H2h[(size_t)ss * 32 + lane]);
            acc = fmaf(ww, hv, acc);
        }
    }
#pragma unroll
    for (int o = 16; o; o >>= 1) den += __shfl_xor_sync(0xffffffffu, den, o);
    float inv = 1.f / den;
    out[(size_t)node * 32 + lane] = fmaf(acc, inv, b2[lane]);
}

// ---------------- launch ----------------
extern "C" void kernel_launch(void* const* d_in, const int* in_sizes, int n_in,
                              void* d_out, int out_size) {
    const float* x    = (const float*)d_in[0];
    const int*   ei   = (const int*)d_in[1];
    const float* W1   = (const float*)d_in[2];
    const float* as1  = (const float*)d_in[3];
    const float* ad1  = (const float*)d_in[4];
    const float* b1   = (const float*)d_in[5];
    const float* W2   = (const float*)d_in[6];
    const float* as2  = (const float*)d_in[7];
    const float* ad2  = (const float*)d_in[8];
    const float* b2   = (const float*)d_in[9];
    float* out = (float*)d_out;

    __half* H1h; cudaGetSymbolAddress((void**)&H1h, g_H1h);
    __half* G1h; cudaGetSymbolAddress((void**)&G1h, g_G1h);
    __half* H2h; cudaGetSymbolAddress((void**)&H2h, g_H2h);
    float*  AS1; cudaGetSymbolAddress((void**)&AS1, g_AS1);
    float*  AD1; cudaGetSymbolAddress((void**)&AD1, g_AD1);
    float*  AS2; cudaGetSymbolAddress((void**)&AS2, g_AS2);
    float*  AD2; cudaGetSymbolAddress((void**)&AD2, g_AD2);

    constexpr int GB = (NN + 63) / 64;   // 1563 GEMM blocks
    constexpr int HB = 782;              // hist blocks
    const int NB = (NN + 1023) / 1024;   // 98 scan blocks
    const int smem1 = (64 * 136 + 128 * 136) * 2;   // 52224 B
    const int smem2 = (128 * 136 + 128 * 40) * 2;   // 45056 B

    cudaFuncSetAttribute((const void*)gemm1_hist_kernel<GB, HB>,
                         cudaFuncAttributeMaxDynamicSharedMemorySize, smem1);
    cudaFuncSetAttribute((const void*)hgemm_kernel<__half, 128, 32, 8, 1, 1>,
                         cudaFuncAttributeMaxDynamicSharedMemorySize, smem2);

    gemm1_hist_kernel<GB, HB>                                         // 0: GEMM1 + hist
        <<<GB + HB, 256, smem1>>>(x, W1, H1h, as1, ad1, AS1, AD1, NN, ei);
    scan_blocks_kernel<<<NB, 1024>>>(NN);                             // 1
    scan_addtop_kernel<<<(NN + 255) / 256, 256>>>(NB, NN);            // 2
    scatter_kernel<<<(ET + 255) / 256, 256>>>(ei);                    // 3 <- profiled
    agg1_kernel<<<(NN * 32 + 255) / 256, 256>>>(b1);                  // 4
    hgemm_kernel<__half, 128, 32, 8, 1, 1>                            // 5
        <<<(NN + 127) / 128, 256, smem2>>>(G1h, W2, H2h, as2, ad2, AS2, AD2, NN);
    agg2_kernel<<<(NN * 32 + 255) / 256, 256>>>(b2, out);             // 6
}